// round 10
// baseline (speedup 1.0000x reference)
#include <cuda_runtime.h>
#include <stdint.h>

// Shapes (fixed by the problem): k (1,32,64,256,256) fp32, mask (64,256,256) int32
#define ALPHA 0.5f
#define BETA  0.25f

constexpr int NC = 32;
constexpr int NT = 64;
constexpr int NX = 256;
constexpr int NY = 256;
constexpr int SPATIAL = NX * NY;              // 65536 elems per t-slice
constexpr int SPAT4   = SPATIAL / 4;          // 16384 int4/uchar4 per t-slice
constexpr long PLANE  = (long)NT * SPATIAL;   // elems per channel

// 4 MiB selector scratch: 0 = zero, 1 = k[t], 2 = ALPHA*k[t-1], 3 = BETA*k[t+1]
__device__ unsigned char g_sel[NT * SPATIAL];

// ---------------------------------------------------------------------------
// Kernel 1: mask (64,256,256) int32 -> selector byte per site. Vectorized:
// each thread handles 4 sites (int4 loads x3, uchar4 store). blockIdx.y = t
// so no integer division is needed.
//   m_cur                          -> sel 1  (k)
//   !m_cur & m_prev                -> sel 2  (ALPHA*k_prev)
//   m_next & !(m_prev | m_cur)     -> sel 3  (BETA*k_next)
// (mutually exclusive by construction)
// ---------------------------------------------------------------------------
__global__ __launch_bounds__(256)
void sel_kernel(const int4* __restrict__ mask) {
    int t = blockIdx.y;
    int i = blockIdx.x * blockDim.x + threadIdx.x;   // 0 .. SPAT4-1
    int idx = t * SPAT4 + i;

    int4 cur  = mask[idx];
    int4 prev = (t > 0)      ? mask[idx - SPAT4] : make_int4(0, 0, 0, 0);
    int4 next = (t < NT - 1) ? mask[idx + SPAT4] : make_int4(0, 0, 0, 0);

    uchar4 s;
    s.x = cur.x ? 1u : (prev.x ? 2u : (next.x ? 3u : 0u));
    s.y = cur.y ? 1u : (prev.y ? 2u : (next.y ? 3u : 0u));
    s.z = cur.z ? 1u : (prev.z ? 2u : (next.z ? 3u : 0u));
    s.w = cur.w ? 1u : (prev.w ? 2u : (next.w ? 3u : 0u));

    reinterpret_cast<uchar4*>(g_sel)[idx] = s;
}

// ---------------------------------------------------------------------------
// Kernel 2: each thread owns (c, x, 4 consecutive y) and walks t with
// register-carried kp/kc/kn float4 -> every k element read exactly once.
// k/out use streaming hints (.cs) so L2 stays reserved for the 4 MiB
// selector array (reused across all 32 channels).
// ---------------------------------------------------------------------------
__device__ __forceinline__ float4 sel_apply(uchar4 s, float4 kp, float4 kc, float4 kn) {
    float4 o;
    o.x = (s.x == 1) ? kc.x : (s.x == 2) ? ALPHA * kp.x : (s.x == 3) ? BETA * kn.x : 0.f;
    o.y = (s.y == 1) ? kc.y : (s.y == 2) ? ALPHA * kp.y : (s.y == 3) ? BETA * kn.y : 0.f;
    o.z = (s.z == 1) ? kc.z : (s.z == 2) ? ALPHA * kp.z : (s.z == 3) ? BETA * kn.z : 0.f;
    o.w = (s.w == 1) ? kc.w : (s.w == 2) ? ALPHA * kp.w : (s.w == 3) ? BETA * kn.w : 0.f;
    return o;
}

__global__ __launch_bounds__(256)
void apply_kernel(const float* __restrict__ k, float* __restrict__ out) {
    constexpr int NY4 = NY / 4;                       // 64 float4 per row
    int tid = blockIdx.x * blockDim.x + threadIdx.x;  // over NC*NX*NY4 (exact multiple)

    int y4 = tid % NY4;
    int xc = tid / NY4;
    int x  = xc % NX;
    int c  = xc / NX;

    long base  = (long)c * PLANE + (long)x * NY + (long)y4 * 4; // k/out index @ t=0
    int  sbase = x * NY + y4 * 4;                               // selector index @ t=0

    float4 kp = make_float4(0.f, 0.f, 0.f, 0.f);
    float4 kc = __ldcs(reinterpret_cast<const float4*>(k + base));

    // Main loop: t = 0 .. NT-2 always has a valid t+1 load (no branch).
    #pragma unroll 8
    for (int t = 0; t < NT - 1; ++t) {
        float4 kn = __ldcs(reinterpret_cast<const float4*>(k + base + (long)(t + 1) * SPATIAL));
        uchar4 s  = *reinterpret_cast<const uchar4*>(g_sel + sbase + t * SPATIAL);
        float4 o  = sel_apply(s, kp, kc, kn);
        __stcs(reinterpret_cast<float4*>(out + base + (long)t * SPATIAL), o);
        kp = kc;
        kc = kn;
    }

    // Epilogue t = NT-1: k_next is zero-padded.
    {
        const int t = NT - 1;
        float4 kn = make_float4(0.f, 0.f, 0.f, 0.f);
        uchar4 s  = *reinterpret_cast<const uchar4*>(g_sel + sbase + t * SPATIAL);
        float4 o  = sel_apply(s, kp, kc, kn);
        __stcs(reinterpret_cast<float4*>(out + base + (long)t * SPATIAL), o);
    }
}

extern "C" void kernel_launch(void* const* d_in, const int* in_sizes, int n_in,
                              void* d_out, int out_size) {
    const float* k    = (const float*)d_in[0];
    const int*   mask = (const int*)d_in[1];
    float*       out  = (float*)d_out;

    // Kernel 1: selector bytes (4 MiB), vectorized
    {
        dim3 grid(SPAT4 / 256, NT);   // (64, 64)
        sel_kernel<<<grid, 256>>>(reinterpret_cast<const int4*>(mask));
    }

    // Kernel 2: streaming apply
    {
        int n = NC * NX * (NY / 4);   // 524288 threads, exact multiple of 256
        apply_kernel<<<n / 256, 256>>>(k, out);
    }
}

// round 11
// speedup vs baseline: 1.1999x; 1.1999x over previous
#include <cuda_runtime.h>
#include <stdint.h>

// Shapes (fixed by the problem): k (1,32,64,256,256) fp32, mask (64,256,256) int32
#define ALPHA 0.5f
#define BETA  0.25f

constexpr int NC = 32;
constexpr int NT = 64;
constexpr int NX = 256;
constexpr int NY = 256;
constexpr int SPATIAL = NX * NY;              // 65536 elems per t-slice
constexpr int SPAT4   = SPATIAL / 4;          // 16384 int4/uchar4 per t-slice
constexpr long PLANE  = (long)NT * SPATIAL;   // elems per channel

// 4 MiB selector scratch: 0 = zero, 1 = k[t], 2 = ALPHA*k[t-1], 3 = BETA*k[t+1]
__device__ unsigned char g_sel[NT * SPATIAL];

// ---------------------------------------------------------------------------
// Kernel 1: mask (64,256,256) int32 -> selector byte per site. Vectorized:
// each thread handles 4 sites (int4 loads x3, uchar4 store). blockIdx.y = t
// so no integer division is needed.
//   m_cur                          -> sel 1  (k)
//   !m_cur & m_prev                -> sel 2  (ALPHA*k_prev)
//   m_next & !(m_prev | m_cur)     -> sel 3  (BETA*k_next)
// (mutually exclusive by construction)
// ---------------------------------------------------------------------------
__global__ __launch_bounds__(256)
void sel_kernel(const int4* __restrict__ mask) {
    int t = blockIdx.y;
    int i = blockIdx.x * blockDim.x + threadIdx.x;   // 0 .. SPAT4-1
    int idx = t * SPAT4 + i;

    int4 cur  = mask[idx];
    int4 prev = (t > 0)      ? mask[idx - SPAT4] : make_int4(0, 0, 0, 0);
    int4 next = (t < NT - 1) ? mask[idx + SPAT4] : make_int4(0, 0, 0, 0);

    uchar4 s;
    s.x = cur.x ? 1u : (prev.x ? 2u : (next.x ? 3u : 0u));
    s.y = cur.y ? 1u : (prev.y ? 2u : (next.y ? 3u : 0u));
    s.z = cur.z ? 1u : (prev.z ? 2u : (next.z ? 3u : 0u));
    s.w = cur.w ? 1u : (prev.w ? 2u : (next.w ? 3u : 0u));

    reinterpret_cast<uchar4*>(g_sel)[idx] = s;
}

// ---------------------------------------------------------------------------
// Kernel 2: each thread owns (c, x, 4 consecutive y) and walks t with
// register-carried kp/kc/kn float4 -> every k element read exactly once.
// __launch_bounds__(256, 8) caps regs at 32 -> 8 CTAs/SM -> full occupancy;
// occupancy (warp count) is the MLP source here, per R10's post-mortem.
// ---------------------------------------------------------------------------
__device__ __forceinline__ float4 sel_apply(uchar4 s, float4 kp, float4 kc, float4 kn) {
    float4 o;
    o.x = (s.x == 1) ? kc.x : (s.x == 2) ? ALPHA * kp.x : (s.x == 3) ? BETA * kn.x : 0.f;
    o.y = (s.y == 1) ? kc.y : (s.y == 2) ? ALPHA * kp.y : (s.y == 3) ? BETA * kn.y : 0.f;
    o.z = (s.z == 1) ? kc.z : (s.z == 2) ? ALPHA * kp.z : (s.z == 3) ? BETA * kn.z : 0.f;
    o.w = (s.w == 1) ? kc.w : (s.w == 2) ? ALPHA * kp.w : (s.w == 3) ? BETA * kn.w : 0.f;
    return o;
}

__global__ __launch_bounds__(256, 8)
void apply_kernel(const float* __restrict__ k, float* __restrict__ out) {
    constexpr int NY4 = NY / 4;                       // 64 float4 per row
    int tid = blockIdx.x * blockDim.x + threadIdx.x;  // over NC*NX*NY4 (exact multiple)

    int y4 = tid % NY4;
    int xc = tid / NY4;
    int x  = xc % NX;
    int c  = xc / NX;

    long base  = (long)c * PLANE + (long)x * NY + (long)y4 * 4; // k/out index @ t=0
    int  sbase = x * NY + y4 * 4;                               // selector index @ t=0

    float4 kp = make_float4(0.f, 0.f, 0.f, 0.f);
    float4 kc = __ldcs(reinterpret_cast<const float4*>(k + base));

    // Main loop: t = 0 .. NT-2 always has a valid t+1 load (no branch).
    #pragma unroll 4
    for (int t = 0; t < NT - 1; ++t) {
        float4 kn = __ldcs(reinterpret_cast<const float4*>(k + base + (long)(t + 1) * SPATIAL));
        uchar4 s  = *reinterpret_cast<const uchar4*>(g_sel + sbase + t * SPATIAL);
        float4 o  = sel_apply(s, kp, kc, kn);
        __stcs(reinterpret_cast<float4*>(out + base + (long)t * SPATIAL), o);
        kp = kc;
        kc = kn;
    }

    // Epilogue t = NT-1: k_next is zero-padded.
    {
        const int t = NT - 1;
        float4 kn = make_float4(0.f, 0.f, 0.f, 0.f);
        uchar4 s  = *reinterpret_cast<const uchar4*>(g_sel + sbase + t * SPATIAL);
        float4 o  = sel_apply(s, kp, kc, kn);
        __stcs(reinterpret_cast<float4*>(out + base + (long)t * SPATIAL), o);
    }
}

extern "C" void kernel_launch(void* const* d_in, const int* in_sizes, int n_in,
                              void* d_out, int out_size) {
    const float* k    = (const float*)d_in[0];
    const int*   mask = (const int*)d_in[1];
    float*       out  = (float*)d_out;

    // Kernel 1: selector bytes (4 MiB), vectorized
    {
        dim3 grid(SPAT4 / 256, NT);   // (64, 64)
        sel_kernel<<<grid, 256>>>(reinterpret_cast<const int4*>(mask));
    }

    // Kernel 2: streaming apply
    {
        int n = NC * NX * (NY / 4);   // 524288 threads, exact multiple of 256
        apply_kernel<<<n / 256, 256>>>(k, out);
    }
}